// round 11
// baseline (speedup 1.0000x reference)
#include <cuda_runtime.h>
#include <cuda_fp16.h>
#include <cstdint>

// Problem constants: B=256, D=256, F=512
#define Bc 256
#define Dc 256
#define Fc 512
#define P_T 0.05f

#define DEVARR __device__ __align__(16)
DEVARR __half g_G16[Fc * Fc];    // G fp16, rows i, cols j
DEVARR __half g_wf16[Dc * Fc];   // wf fp16 (converted by mma1 aux CTAs)
DEVARR float g_XZ[Dc * Fc];      // mean_b x z
DEVARR float g_zbar[Fc];
DEVARR float g_rpart[4][Fc];     // G row-sum partials per 128-col chunk (raw)
DEVARR float g_diag[Fc];         // p - mu_t[i,i]

__device__ __forceinline__ uint32_t smem_u32(const void* p) {
    uint32_t a;
    asm("{ .reg .u64 t; cvta.to.shared.u64 t, %1; cvt.u32.u64 %0, t; }"
        : "=r"(a) : "l"(p));
    return a;
}
// m16n8k16 f16 MMA, fp32 accumulate (verified R7-R9)
__device__ __forceinline__ void mma16816(float* c, const uint32_t* a, const uint32_t* b) {
    asm volatile(
        "mma.sync.aligned.m16n8k16.row.col.f32.f16.f16.f32 "
        "{%0,%1,%2,%3}, {%4,%5,%6,%7}, {%8,%9}, {%0,%1,%2,%3};"
        : "+f"(c[0]), "+f"(c[1]), "+f"(c[2]), "+f"(c[3])
        : "r"(a[0]), "r"(a[1]), "r"(a[2]), "r"(a[3]), "r"(b[0]), "r"(b[1]));
}
__device__ __forceinline__ void ldsm_x4(uint32_t& r0, uint32_t& r1, uint32_t& r2,
                                        uint32_t& r3, uint32_t addr) {
    asm volatile("ldmatrix.sync.aligned.m8n8.x4.shared.b16 {%0,%1,%2,%3}, [%4];"
                 : "=r"(r0), "=r"(r1), "=r"(r2), "=r"(r3) : "r"(addr));
}
__device__ __forceinline__ void ldsm_x4_t(uint32_t& r0, uint32_t& r1, uint32_t& r2,
                                          uint32_t& r3, uint32_t addr) {
    asm volatile("ldmatrix.sync.aligned.m8n8.x4.trans.shared.b16 {%0,%1,%2,%3}, [%4];"
                 : "=r"(r0), "=r"(r1), "=r"(r2), "=r"(r3) : "r"(addr));
}
__device__ __forceinline__ void cp16(uint32_t dst, const void* src) {
    asm volatile("cp.async.cg.shared.global [%0], [%1], 16;" :: "r"(dst), "l"(src));
}
__device__ __forceinline__ void cp_commit() {
    asm volatile("cp.async.commit_group;" ::: "memory");
}
template <int N>
__device__ __forceinline__ void cp_wait() {
    asm volatile("cp.async.wait_group %0;" :: "n"(N) : "memory");
}

// ---------------------------------------------------------------------------
// mma1_k: 56 CTAs x 512 threads, 2 warpgroups splitting K=256 into halves.
//  bb [0,16):  M  = z'z /B  -> dmu, G16, rpart, diag/dbf/dbp
//  bb [16,32): KP = u'td /B -> o_dkp
//  bb [32,40): XZ = x'z /B  -> g_XZ
//  bb [40,56): wf fp32->fp16 + zbar (aux work)
// ---------------------------------------------------------------------------
#define SM1_A 0
#define SM1_B (2 * 32 * 136 * 2)
#define SMEM1 (128 * 130 * 4 + 256)   // stage overlay dominates

__global__ void __launch_bounds__(512) mma1_k(
    const float* __restrict__ z, const float* __restrict__ x,
    const float* __restrict__ u, const float* __restrict__ td,
    const float* __restrict__ mu, const float* __restrict__ wf32,
    float* __restrict__ o_dmu, float* __restrict__ o_dbf,
    float* __restrict__ o_dbp, float* __restrict__ o_dkp)
{
    extern __shared__ __align__(16) char smem[];
    const int bb = blockIdx.x, tid = threadIdx.x;

    if (bb >= 40) {
        // ---- aux: wf fp32->fp16 (16 CTAs x 16384 floats) + zbar (32 cols/CTA)
        const int base = (bb - 40) * 16384 + tid * 4;
#pragma unroll
        for (int q = 0; q < 8; q++) {
            const int off = base + q * 2048;
            float4 v = *(const float4*)&wf32[off];
            __half2 h0 = __floats2half2_rn(v.x, v.y);
            __half2 h1 = __floats2half2_rn(v.z, v.w);
            uint2 pk = {*(uint32_t*)&h0, *(uint32_t*)&h1};
            *(uint2*)&g_wf16[off] = pk;
        }
        float* s_z = (float*)smem;               // [16][33]
        const int zc = tid & 31, zr = tid >> 5;  // zr 0..15
        const int col = (bb - 40) * 32 + zc;
        float s = 0.f;
#pragma unroll
        for (int i = 0; i < 16; i++) s += z[(zr + 16 * i) * Fc + col];
        s_z[zr * 33 + zc] = s;
        __syncthreads();
        if (tid < 32) {
            float t = 0.f;
#pragma unroll
            for (int p = 0; p < 16; p++) t += s_z[p * 33 + tid];
            g_zbar[(bb - 40) * 32 + tid] = t * (1.0f / Bc);
        }
        return;
    }

    __half* As = (__half*)(smem + SM1_A);   // [2 groups][32][136]
    __half* Bs = (__half*)(smem + SM1_B);
    __shared__ float s_rsum[128];

    const int g = tid >> 8;                  // warpgroup 0/1 (K half)
    const int gtid = tid & 255;
    const int wig = gtid >> 5, lane = tid & 31;
    const int gid = lane >> 2, tig = lane & 3;
    const int wm = wig >> 2, wn = wig & 3;   // 2x4 warp grid within group
    const int q = lane >> 3, r = lane & 7;

    int kind, m0, n0, lda;
    const float *A, *B;
    if (bb < 16)      { kind = 0; int t = bb;      m0 = (t >> 2) * 128; n0 = (t & 3) * 128; A = z; B = z;  lda = Fc; }
    else if (bb < 32) { kind = 1; int t = bb - 16; m0 = (t >> 2) * 128; n0 = (t & 3) * 128; A = u; B = td; lda = Fc; }
    else              { kind = 2; int t = bb - 32; m0 = (t >> 2) * 128; n0 = (t & 3) * 128; A = x; B = z;  lda = Dc; }

    if (tid < 128) s_rsum[tid] = 0.f;

    float acc[4][4][4];
#pragma unroll
    for (int i = 0; i < 4; i++)
#pragma unroll
        for (int j = 0; j < 4; j++)
#pragma unroll
            for (int p = 0; p < 4; p++) acc[i][j][p] = 0.f;

    __half* gAs = As + g * (32 * 136);
    __half* gBs = Bs + g * (32 * 136);
    const uint32_t smA = smem_u32(gAs), smB = smem_u32(gBs);
    const uint32_t aLane = (uint32_t)(((((q & 2) ? 8 : 0) + r) * 136 + ((q & 1) ? 8 : 0)) * 2);
    const uint32_t bLane = (uint32_t)(((((q & 1) ? 8 : 0) + r) * 136 + ((q & 2) ? 8 : 0)) * 2);

    const int prow = gtid >> 3;              // 0..31
    const int pcol = (gtid & 7) * 16;        // 0..112 step 16
    const int kbase = g * 128;

    float4 pa[4], pb[4];
#pragma unroll
    for (int qq = 0; qq < 4; qq++) {
        pa[qq] = *(const float4*)&A[(kbase + prow) * lda + m0 + pcol + 4 * qq];
        pb[qq] = *(const float4*)&B[(kbase + prow) * Fc  + n0 + pcol + 4 * qq];
    }

#pragma unroll
    for (int jb = 0; jb < 4; jb++) {
#pragma unroll
        for (int qq = 0; qq < 4; qq++) {
            float4 v = pa[qq];
            __half2 h0 = __floats2half2_rn(v.x, v.y);
            __half2 h1 = __floats2half2_rn(v.z, v.w);
            uint2 pk = {*(uint32_t*)&h0, *(uint32_t*)&h1};
            *(uint2*)&gAs[prow * 136 + pcol + 4 * qq] = pk;
            float4 w = pb[qq];
            __half2 g0 = __floats2half2_rn(w.x, w.y);
            __half2 g1 = __floats2half2_rn(w.z, w.w);
            uint2 qk = {*(uint32_t*)&g0, *(uint32_t*)&g1};
            *(uint2*)&gBs[prow * 136 + pcol + 4 * qq] = qk;
        }
        __syncthreads();
        if (jb < 3) {
            const int kr = kbase + (jb + 1) * 32 + prow;
#pragma unroll
            for (int qq = 0; qq < 4; qq++) {
                pa[qq] = *(const float4*)&A[kr * lda + m0 + pcol + 4 * qq];
                pb[qq] = *(const float4*)&B[kr * Fc  + n0 + pcol + 4 * qq];
            }
        }
#pragma unroll
        for (int ks = 0; ks < 2; ks++) {
            const uint32_t koff = (uint32_t)(ks * 16) * 136u * 2u;
            uint32_t a[4][4], b[4][2];
#pragma unroll
            for (int mf = 0; mf < 4; mf++) {
                uint32_t addr = smA + aLane + koff + (uint32_t)(wm * 64 + mf * 16) * 2u;
                ldsm_x4_t(a[mf][0], a[mf][1], a[mf][2], a[mf][3], addr);
            }
#pragma unroll
            for (int np = 0; np < 2; np++) {
                uint32_t t0, t1, t2, t3;
                uint32_t addr = smB + bLane + koff + (uint32_t)(wn * 32 + np * 16) * 2u;
                ldsm_x4_t(t0, t1, t2, t3, addr);
                b[2 * np][0] = t0; b[2 * np][1] = t1;
                b[2 * np + 1][0] = t2; b[2 * np + 1][1] = t3;
            }
#pragma unroll
            for (int mf = 0; mf < 4; mf++)
#pragma unroll
                for (int nf = 0; nf < 4; nf++)
                    mma16816(acc[mf][nf], a[mf], b[nf]);
        }
        __syncthreads();
    }

    // ---- combine: group1 stages accs; group0 adds + runs verified epilogue
    float* stage = (float*)smem;             // [128][130], overlays panels
    if (g == 1) {
#pragma unroll
        for (int mf = 0; mf < 4; mf++)
#pragma unroll
            for (int h = 0; h < 2; h++) {
                const int rr = wm * 64 + mf * 16 + gid + h * 8;
#pragma unroll
                for (int nf = 0; nf < 4; nf++) {
                    const int cc = wn * 32 + nf * 8 + 2 * tig;
                    float2 v = {acc[mf][nf][h * 2 + 0], acc[mf][nf][h * 2 + 1]};
                    *(float2*)&stage[rr * 130 + cc] = v;
                }
            }
    }
    __syncthreads();

    if (g == 0) {
        const int mw = m0 + wm * 64, nw = n0 + wn * 32;
        const float invB = 1.0f / Bc;
#pragma unroll
        for (int mf = 0; mf < 4; mf++) {
#pragma unroll
            for (int h = 0; h < 2; h++) {
                const int gr = mw + mf * 16 + gid + h * 8;
                float rowsum = 0.f;
#pragma unroll
                for (int nf = 0; nf < 4; nf++) {
                    const int gc = nw + nf * 8 + 2 * tig;
                    const int idx = gr * Fc + gc;
                    const int rr = gr - m0, cc = gc - n0;
                    float2 st = *(const float2*)&stage[rr * 130 + cc];
                    float v0 = acc[mf][nf][h * 2 + 0] + st.x;
                    float v1 = acc[mf][nf][h * 2 + 1] + st.y;
                    if (kind == 0) {
                        float raw0 = v0 * invB, raw1 = v1 * invB;
                        float2 muv = *(const float2*)&mu[idx];
                        float mut0 = 0.95f * muv.x + 0.05f * raw0;
                        float mut1 = 0.95f * muv.y + 0.05f * raw1;
                        float2 dm = {0.05f * (raw0 - muv.x), 0.05f * (raw1 - muv.y)};
                        *(float2*)&o_dmu[idx] = dm;
                        float G0 = (P_T * P_T - mut0) * raw0;
                        float G1 = (P_T * P_T - mut1) * raw1;
                        *(__half2*)&g_G16[idx] = __floats2half2_rn(G0, G1);
                        rowsum += G0 + G1;
                        if (m0 == n0) {
                            if (gr == gc) {
                                float db = P_T - mut0;
                                g_diag[gr] = db; o_dbf[gr] = db; o_dbp[gr] = db;
                            } else if (gr == gc + 1) {
                                float db = P_T - mut1;
                                g_diag[gr] = db; o_dbf[gr] = db; o_dbp[gr] = db;
                            }
                        }
                    } else if (kind == 1) {
                        float2 o = {v0 * invB, v1 * invB};
                        *(float2*)&o_dkp[idx] = o;
                    } else {
                        float2 o = {v0 * invB, v1 * invB};
                        *(float2*)&g_XZ[idx] = o;
                    }
                }
                if (kind == 0) {
                    rowsum += __shfl_xor_sync(0xffffffffu, rowsum, 1);
                    rowsum += __shfl_xor_sync(0xffffffffu, rowsum, 2);
                    if (tig == 0) atomicAdd(&s_rsum[gr - m0], rowsum);
                }
            }
        }
    }
    if (kind == 0) {
        __syncthreads();
        if (tid < 128) g_rpart[n0 >> 7][m0 + tid] = s_rsum[tid];
    }
}

// ---------------------------------------------------------------------------
// mma2_k: 32 CTAs x 1024 threads; 4 warpgroups splitting K=512 into quarters
// (2 cp.async double-buffered k-blocks of 64 each). Combine: group0 STORES
// its accs into a stage that OVERLAYS the dead panel buffers, groups 1-3
// atomicAdd, then group0 runs the verified dkf epilogue. 147456 B smem.
// ---------------------------------------------------------------------------
#define PB2 (64 * 72)                       // halves per panel buffer
#define SM2_B (8 * PB2 * 2)                 // 73728
#define SMEM2 (16 * PB2 * 2)                // 147456

__global__ void __launch_bounds__(1024) mma2_k(
    const float* __restrict__ wf32, float* __restrict__ o_dkf)
{
    extern __shared__ __align__(16) char smem[];
    __shared__ float s_diag[64], s_zbar[64], s_r[64];

    const int bb = blockIdx.x, tid = threadIdx.x;
    const int g = tid >> 8;                  // warpgroup 0..3 (K quarter)
    const int gtid = tid & 255;
    const int wig = gtid >> 5, lane = tid & 31;
    const int gid = lane >> 2, tig = lane & 3;
    const int wm = wig >> 2, wn = wig & 3;   // 2x4 warp grid within group
    const int q = lane >> 3, r = lane & 7;

    const int d0 = (bb >> 3) * 64;
    const int n0 = (bb & 7) * 64;

    if (tid < 64) {
        int i = n0 + tid;
        s_zbar[tid] = g_zbar[i];
        float rr = 0.f;
#pragma unroll
        for (int p = 0; p < 4; p++) rr += g_rpart[p][i];
        s_r[tid] = rr * (1.0f / Fc);
        s_diag[tid] = g_diag[i];
    }

    float acc[2][2][4];
#pragma unroll
    for (int i = 0; i < 2; i++)
#pragma unroll
        for (int j = 0; j < 2; j++)
#pragma unroll
            for (int p = 0; p < 4; p++) acc[i][j][p] = 0.f;

    const uint32_t smBase = smem_u32(smem);
    const uint32_t aLane = (uint32_t)(((((q & 1) ? 8 : 0) + r) * 72 + ((q & 2) ? 8 : 0)) * 2);
    const uint32_t bLane = (uint32_t)(((((q & 2) ? 8 : 0) + r) * 72 + ((q & 1) ? 8 : 0)) * 2);

    const int prow = gtid >> 2, pcol = (gtid & 3) * 16;
    const uint32_t pdst = (uint32_t)(prow * 72 + pcol) * 2u;
    const int kbase = g * 128;

    // buffer byte offsets for this group
    const uint32_t aOff0 = (uint32_t)((g * 2 + 0) * PB2 * 2);
    const uint32_t aOff1 = (uint32_t)((g * 2 + 1) * PB2 * 2);
    const uint32_t bOff0 = (uint32_t)(SM2_B + (g * 2 + 0) * PB2 * 2);
    const uint32_t bOff1 = (uint32_t)(SM2_B + (g * 2 + 1) * PB2 * 2);

    // issue buffer 0 (k = kbase)
    {
        const __half* sa = g_wf16 + (d0 + prow) * Fc + kbase + pcol;
        const __half* sb = g_G16  + (n0 + prow) * Fc + kbase + pcol;
        cp16(smBase + aOff0 + pdst, sa); cp16(smBase + aOff0 + pdst + 16, sa + 8);
        cp16(smBase + bOff0 + pdst, sb); cp16(smBase + bOff0 + pdst + 16, sb + 8);
        cp_commit();
    }
    // issue buffer 1 (k = kbase + 64)
    {
        const __half* sa = g_wf16 + (d0 + prow) * Fc + kbase + 64 + pcol;
        const __half* sb = g_G16  + (n0 + prow) * Fc + kbase + 64 + pcol;
        cp16(smBase + aOff1 + pdst, sa); cp16(smBase + aOff1 + pdst + 16, sa + 8);
        cp16(smBase + bOff1 + pdst, sb); cp16(smBase + bOff1 + pdst + 16, sb + 8);
        cp_commit();
    }

#pragma unroll
    for (int jb = 0; jb < 2; jb++) {
        if (jb == 0) cp_wait<1>();
        else         cp_wait<0>();
        __syncthreads();

        const uint32_t aB = smBase + (jb ? aOff1 : aOff0);
        const uint32_t bB = smBase + (jb ? bOff1 : bOff0);
#pragma unroll
        for (int ks = 0; ks < 4; ks++) {
            const uint32_t koff = (uint32_t)(ks * 16) * 2u;
            uint32_t a[2][4], b[2][2];
#pragma unroll
            for (int mf = 0; mf < 2; mf++) {
                uint32_t addr = aB + aLane + (uint32_t)((wm * 32 + mf * 16) * 72) * 2u + koff;
                ldsm_x4(a[mf][0], a[mf][1], a[mf][2], a[mf][3], addr);
            }
            {
                uint32_t t0, t1, t2, t3;
                uint32_t addr = bB + bLane + (uint32_t)((wn * 16) * 72) * 2u + koff;
                ldsm_x4(t0, t1, t2, t3, addr);
                b[0][0] = t0; b[0][1] = t1; b[1][0] = t2; b[1][1] = t3;
            }
#pragma unroll
            for (int mf = 0; mf < 2; mf++)
#pragma unroll
                for (int nf = 0; nf < 2; nf++)
                    mma16816(acc[mf][nf], a[mf], b[nf]);
        }
        __syncthreads();
    }

    // ---- combine into stage (overlays dead panel buffers)
    float* stage = (float*)smem;             // [64][66]
    if (g == 0) {
#pragma unroll
        for (int mf = 0; mf < 2; mf++)
#pragma unroll
            for (int h = 0; h < 2; h++) {
                const int rr = wm * 32 + mf * 16 + gid + h * 8;
#pragma unroll
                for (int nf = 0; nf < 2; nf++) {
                    const int cc = wn * 16 + nf * 8 + 2 * tig;
                    stage[rr * 66 + cc]     = acc[mf][nf][h * 2 + 0];
                    stage[rr * 66 + cc + 1] = acc[mf][nf][h * 2 + 1];
                }
            }
    }
    __syncthreads();
    if (g != 0) {
#pragma unroll
        for (int mf = 0; mf < 2; mf++)
#pragma unroll
            for (int h = 0; h < 2; h++) {
                const int rr = wm * 32 + mf * 16 + gid + h * 8;
#pragma unroll
                for (int nf = 0; nf < 2; nf++) {
                    const int cc = wn * 16 + nf * 8 + 2 * tig;
                    atomicAdd(&stage[rr * 66 + cc],     acc[mf][nf][h * 2 + 0]);
                    atomicAdd(&stage[rr * 66 + cc + 1], acc[mf][nf][h * 2 + 1]);
                }
            }
    }
    __syncthreads();

    if (g == 0) {
        const float invF = 1.0f / Fc;
        const int mw = d0 + wm * 32, nw = n0 + wn * 16;
#pragma unroll
        for (int mf = 0; mf < 2; mf++) {
#pragma unroll
            for (int h = 0; h < 2; h++) {
                const int gr = mw + mf * 16 + gid + h * 8;
#pragma unroll
                for (int nf = 0; nf < 2; nf++) {
                    const int gc = nw + nf * 8 + 2 * tig;
                    const int idx = gr * Fc + gc;
                    const int cl = gc - n0, rl = gr - d0;
                    float2 cv = *(const float2*)&stage[rl * 66 + cl];
                    float2 wfv = *(const float2*)&wf32[idx];
                    float2 xz  = *(const float2*)&g_XZ[idx];
                    float2 o;
                    o.x = s_diag[cl] * (xz.x - wfv.x * s_zbar[cl])
                        + wfv.x * s_r[cl] - cv.x * invF;
                    o.y = s_diag[cl + 1] * (xz.y - wfv.y * s_zbar[cl + 1])
                        + wfv.y * s_r[cl + 1] - cv.y * invF;
                    *(float2*)&o_dkf[idx] = o;
                }
            }
        }
    }
}

extern "C" void kernel_launch(void* const* d_in, const int* in_sizes, int n_in,
                              void* d_out, int out_size)
{
    const float* z  = (const float*)d_in[0];   // (B,F)
    const float* x  = (const float*)d_in[1];   // (B,D)
    const float* u  = (const float*)d_in[2];   // (B,F)
    const float* td = (const float*)d_in[3];   // (B,F)
    const float* mu = (const float*)d_in[4];   // (F,F)
    const float* wf = (const float*)d_in[5];   // (D,F)

    float* out   = (float*)d_out;
    float* o_dmu = out;                        // F*F
    float* o_dkf = o_dmu + Fc * Fc;            // D*F
    float* o_dbf = o_dkf + Dc * Fc;            // F
    float* o_dkp = o_dbf + Fc;                 // F*F
    float* o_dbp = o_dkp + Fc * Fc;            // F

    cudaFuncSetAttribute(mma1_k, cudaFuncAttributeMaxDynamicSharedMemorySize, SMEM1);
    cudaFuncSetAttribute(mma2_k, cudaFuncAttributeMaxDynamicSharedMemorySize, SMEM2);

    mma1_k<<<56, 512, SMEM1>>>(z, x, u, td, mu, wf, o_dmu, o_dbf, o_dbp, o_dkp);
    mma2_k<<<32, 1024, SMEM2>>>(wf, o_dkf);
}

// round 12
// speedup vs baseline: 1.6989x; 1.6989x over previous
#include <cuda_runtime.h>
#include <cuda_fp16.h>
#include <cstdint>

// Problem constants: B=256, D=256, F=512
#define Bc 256
#define Dc 256
#define Fc 512
#define P_T 0.05f

#define DEVARR __device__ __align__(16)
DEVARR __half g_G16[Fc * Fc];    // G fp16, rows i, cols j
DEVARR __half g_wf16[Dc * Fc];   // wf fp16 (aux CTAs)
DEVARR float g_XZ[Dc * Fc];      // mean_b x z
DEVARR float g_zbar[Fc];
DEVARR float g_rpart[8][Fc];     // G row-sum partials per 64-col chunk (raw)
DEVARR float g_diag[Fc];         // p - mu_t[i,i]

__device__ __forceinline__ uint32_t smem_u32(const void* p) {
    uint32_t a;
    asm("{ .reg .u64 t; cvta.to.shared.u64 t, %1; cvt.u32.u64 %0, t; }"
        : "=r"(a) : "l"(p));
    return a;
}
// m16n8k16 f16 MMA, fp32 accumulate (verified R7-R11)
__device__ __forceinline__ void mma16816(float* c, const uint32_t* a, const uint32_t* b) {
    asm volatile(
        "mma.sync.aligned.m16n8k16.row.col.f32.f16.f16.f32 "
        "{%0,%1,%2,%3}, {%4,%5,%6,%7}, {%8,%9}, {%0,%1,%2,%3};"
        : "+f"(c[0]), "+f"(c[1]), "+f"(c[2]), "+f"(c[3])
        : "r"(a[0]), "r"(a[1]), "r"(a[2]), "r"(a[3]), "r"(b[0]), "r"(b[1]));
}
__device__ __forceinline__ void ldsm_x4(uint32_t& r0, uint32_t& r1, uint32_t& r2,
                                        uint32_t& r3, uint32_t addr) {
    asm volatile("ldmatrix.sync.aligned.m8n8.x4.shared.b16 {%0,%1,%2,%3}, [%4];"
                 : "=r"(r0), "=r"(r1), "=r"(r2), "=r"(r3) : "r"(addr));
}
__device__ __forceinline__ void ldsm_x4_t(uint32_t& r0, uint32_t& r1, uint32_t& r2,
                                          uint32_t& r3, uint32_t addr) {
    asm volatile("ldmatrix.sync.aligned.m8n8.x4.trans.shared.b16 {%0,%1,%2,%3}, [%4];"
                 : "=r"(r0), "=r"(r1), "=r"(r2), "=r"(r3) : "r"(addr));
}
__device__ __forceinline__ void cp16(uint32_t dst, const void* src) {
    asm volatile("cp.async.cg.shared.global [%0], [%1], 16;" :: "r"(dst), "l"(src));
}
__device__ __forceinline__ void cp_commit() {
    asm volatile("cp.async.commit_group;" ::: "memory");
}
template <int N>
__device__ __forceinline__ void cp_wait() {
    asm volatile("cp.async.wait_group %0;" :: "n"(N) : "memory");
}

// ---------------------------------------------------------------------------
// mma1_k: 176 CTAs x 256 threads. 64x64 output tiles, K=256 (4 blocks of 64),
// register-prefetch pipeline, ldmatrix.trans fragments (verified).
//  bb [0,64):    M  = z'z /B  -> dmu, G16, rpart, diag/dbf/dbp
//  bb [64,128):  KP = u'td /B -> o_dkp
//  bb [128,160): XZ = x'z /B  -> g_XZ
//  bb [160,176): aux: wf fp32->fp16 + zbar
// 8 warps (2x4), warp tile 32x16 (mf=2, nf=2).
// ---------------------------------------------------------------------------
__global__ void __launch_bounds__(256) mma1_k(
    const float* __restrict__ z, const float* __restrict__ x,
    const float* __restrict__ u, const float* __restrict__ td,
    const float* __restrict__ mu, const float* __restrict__ wf32,
    float* __restrict__ o_dmu, float* __restrict__ o_dbf,
    float* __restrict__ o_dbp, float* __restrict__ o_dkp)
{
    __shared__ __align__(16) __half As[64][72];   // [k][m]
    __shared__ __align__(16) __half Bs[64][72];   // [k][n]
    __shared__ float s_rsum[64];
    __shared__ float s_z[8][33];

    const int bb = blockIdx.x, tid = threadIdx.x;

    if (bb >= 160) {
        // ---- aux: wf fp32->fp16 (16 CTAs x 16384 floats) + zbar (32 cols/CTA)
        const int base = (bb - 160) * 16384 + tid * 4;
#pragma unroll
        for (int q = 0; q < 16; q++) {
            const int off = base + q * 1024;
            float4 v = *(const float4*)&wf32[off];
            __half2 h0 = __floats2half2_rn(v.x, v.y);
            __half2 h1 = __floats2half2_rn(v.z, v.w);
            uint2 pk = {*(uint32_t*)&h0, *(uint32_t*)&h1};
            *(uint2*)&g_wf16[off] = pk;
        }
        const int zc = tid & 31, zr = tid >> 5;   // zr 0..7
        const int col = (bb - 160) * 32 + zc;
        float s = 0.f;
#pragma unroll
        for (int i = 0; i < 32; i++) s += z[(zr + 8 * i) * Fc + col];
        s_z[zr][zc] = s;
        __syncthreads();
        if (tid < 32) {
            float t = 0.f;
#pragma unroll
            for (int p = 0; p < 8; p++) t += s_z[p][tid];
            g_zbar[(bb - 160) * 32 + tid] = t * (1.0f / Bc);
        }
        return;
    }

    const int wig = tid >> 5, lane = tid & 31;
    const int gid = lane >> 2, tig = lane & 3;
    const int wm = wig >> 2, wn = wig & 3;        // 2x4 warp grid
    const int q = lane >> 3, r = lane & 7;

    int kind, m0, n0, lda;
    const float *A, *B;
    if (bb < 64)       { kind = 0; int t = bb;       m0 = (t >> 3) * 64; n0 = (t & 7) * 64; A = z; B = z;  lda = Fc; }
    else if (bb < 128) { kind = 1; int t = bb - 64;  m0 = (t >> 3) * 64; n0 = (t & 7) * 64; A = u; B = td; lda = Fc; }
    else               { kind = 2; int t = bb - 128; m0 = (t >> 3) * 64; n0 = (t & 7) * 64; A = x; B = z;  lda = Dc; }

    if (tid < 64) s_rsum[tid] = 0.f;

    float acc[2][2][4];
#pragma unroll
    for (int i = 0; i < 2; i++)
#pragma unroll
        for (int j = 0; j < 2; j++)
#pragma unroll
            for (int p = 0; p < 4; p++) acc[i][j][p] = 0.f;

    const uint32_t smA = smem_u32(As), smB = smem_u32(Bs);
    // ldmatrix.trans lane offsets (stride 72 halves), structure verified at 136
    const uint32_t aLane = (uint32_t)(((((q & 2) ? 8 : 0) + r) * 72 + ((q & 1) ? 8 : 0)) * 2);
    const uint32_t bLane = (uint32_t)(((((q & 1) ? 8 : 0) + r) * 72 + ((q & 2) ? 8 : 0)) * 2);

    // panel load: 64 k-rows x 64 cols, 256 threads -> 16 floats each
    const int prow = tid >> 2;               // 0..63 (k row)
    const int pcol = (tid & 3) * 16;         // 0,16,32,48

    float4 pa[4], pb[4];
#pragma unroll
    for (int qq = 0; qq < 4; qq++) {
        pa[qq] = *(const float4*)&A[prow * lda + m0 + pcol + 4 * qq];
        pb[qq] = *(const float4*)&B[prow * Fc  + n0 + pcol + 4 * qq];
    }

#pragma unroll
    for (int kb = 0; kb < 4; kb++) {
#pragma unroll
        for (int qq = 0; qq < 4; qq++) {
            float4 v = pa[qq];
            __half2 h0 = __floats2half2_rn(v.x, v.y);
            __half2 h1 = __floats2half2_rn(v.z, v.w);
            uint2 pk = {*(uint32_t*)&h0, *(uint32_t*)&h1};
            *(uint2*)&As[prow][pcol + 4 * qq] = pk;
            float4 w = pb[qq];
            __half2 g0 = __floats2half2_rn(w.x, w.y);
            __half2 g1 = __floats2half2_rn(w.z, w.w);
            uint2 qk = {*(uint32_t*)&g0, *(uint32_t*)&g1};
            *(uint2*)&Bs[prow][pcol + 4 * qq] = qk;
        }
        __syncthreads();
        if (kb < 3) {
            const int kr = (kb + 1) * 64 + prow;
#pragma unroll
            for (int qq = 0; qq < 4; qq++) {
                pa[qq] = *(const float4*)&A[kr * lda + m0 + pcol + 4 * qq];
                pb[qq] = *(const float4*)&B[kr * Fc  + n0 + pcol + 4 * qq];
            }
        }
#pragma unroll
        for (int ks = 0; ks < 4; ks++) {
            const uint32_t koff = (uint32_t)(ks * 16) * 72u * 2u;
            uint32_t a[2][4], b[2][2];
#pragma unroll
            for (int mf = 0; mf < 2; mf++) {
                uint32_t addr = smA + aLane + koff + (uint32_t)(wm * 32 + mf * 16) * 2u;
                ldsm_x4_t(a[mf][0], a[mf][1], a[mf][2], a[mf][3], addr);
            }
            {
                uint32_t t0, t1, t2, t3;
                uint32_t addr = smB + bLane + koff + (uint32_t)(wn * 16) * 2u;
                ldsm_x4_t(t0, t1, t2, t3, addr);
                b[0][0] = t0; b[0][1] = t1;
                b[1][0] = t2; b[1][1] = t3;
            }
#pragma unroll
            for (int mf = 0; mf < 2; mf++)
#pragma unroll
                for (int nf = 0; nf < 2; nf++)
                    mma16816(acc[mf][nf], a[mf], b[nf]);
        }
        __syncthreads();
    }

    // Fused epilogue (verified structure)
    const int mw = m0 + wm * 32, nw = n0 + wn * 16;
    const float invB = 1.0f / Bc;
#pragma unroll
    for (int mf = 0; mf < 2; mf++) {
#pragma unroll
        for (int h = 0; h < 2; h++) {
            const int gr = mw + mf * 16 + gid + h * 8;
            float rowsum = 0.f;
#pragma unroll
            for (int nf = 0; nf < 2; nf++) {
                const int gc = nw + nf * 8 + 2 * tig;
                const int idx = gr * Fc + gc;
                float v0 = acc[mf][nf][h * 2 + 0];
                float v1 = acc[mf][nf][h * 2 + 1];
                if (kind == 0) {
                    float raw0 = v0 * invB, raw1 = v1 * invB;
                    float2 muv = *(const float2*)&mu[idx];
                    float mut0 = 0.95f * muv.x + 0.05f * raw0;
                    float mut1 = 0.95f * muv.y + 0.05f * raw1;
                    float2 dm = {0.05f * (raw0 - muv.x), 0.05f * (raw1 - muv.y)};
                    *(float2*)&o_dmu[idx] = dm;
                    float G0 = (P_T * P_T - mut0) * raw0;
                    float G1 = (P_T * P_T - mut1) * raw1;
                    *(__half2*)&g_G16[idx] = __floats2half2_rn(G0, G1);
                    rowsum += G0 + G1;
                    if (m0 == n0) {
                        if (gr == gc) {
                            float db = P_T - mut0;
                            g_diag[gr] = db; o_dbf[gr] = db; o_dbp[gr] = db;
                        } else if (gr == gc + 1) {
                            float db = P_T - mut1;
                            g_diag[gr] = db; o_dbf[gr] = db; o_dbp[gr] = db;
                        }
                    }
                } else if (kind == 1) {
                    float2 o = {v0 * invB, v1 * invB};
                    *(float2*)&o_dkp[idx] = o;
                } else {
                    float2 o = {v0 * invB, v1 * invB};
                    *(float2*)&g_XZ[idx] = o;
                }
            }
            if (kind == 0) {
                rowsum += __shfl_xor_sync(0xffffffffu, rowsum, 1);
                rowsum += __shfl_xor_sync(0xffffffffu, rowsum, 2);
                if (tig == 0) atomicAdd(&s_rsum[gr - m0], rowsum);
            }
        }
    }
    if (kind == 0) {
        __syncthreads();
        if (tid < 64) g_rpart[n0 >> 6][m0 + tid] = s_rsum[tid];
    }
}

// ---------------------------------------------------------------------------
// mma2_k: 128 CTAs x 128 threads. 32x32 tiles, K=512 (8 blocks of 64),
// cp.async double-buffered fp16 panels. 4 warps (2x2), warp 16x16 (nf=2).
// Full dkf epilogue fused, accumulators direct (no split-K).
// ---------------------------------------------------------------------------
__global__ void __launch_bounds__(128) mma2_k(
    const float* __restrict__ wf32, float* __restrict__ o_dkf)
{
    __shared__ __align__(16) __half As[2][32][72];
    __shared__ __align__(16) __half Bs[2][32][72];
    __shared__ float s_diag[32], s_zbar[32], s_r[32];

    const int bb = blockIdx.x, tid = threadIdx.x;
    const int wig = tid >> 5, lane = tid & 31;
    const int gid = lane >> 2, tig = lane & 3;
    const int wm = wig >> 1, wn = wig & 1;        // 2x2 warp grid
    const int q = lane >> 3, r = lane & 7;

    const int d0 = (bb >> 4) * 32;                // 8 d-tiles
    const int n0 = (bb & 15) * 32;                // 16 n-tiles

    if (tid < 32) {
        int i = n0 + tid;
        s_zbar[tid] = g_zbar[i];
        float rr = 0.f;
#pragma unroll
        for (int p = 0; p < 8; p++) rr += g_rpart[p][i];
        s_r[tid] = rr * (1.0f / Fc);
        s_diag[tid] = g_diag[i];
    }

    float acc[2][4];                              // [nf][4]
#pragma unroll
    for (int j = 0; j < 2; j++)
#pragma unroll
        for (int p = 0; p < 4; p++) acc[j][p] = 0.f;

    const uint32_t smA = smem_u32(As), smB = smem_u32(Bs);
    // no-trans lane offsets (stride 72), verified R9
    const uint32_t aLane = (uint32_t)(((((q & 1) ? 8 : 0) + r) * 72 + ((q & 2) ? 8 : 0)) * 2);
    const uint32_t bLane = (uint32_t)(((((q & 2) ? 8 : 0) + r) * 72 + ((q & 1) ? 8 : 0)) * 2);

    // cp.async: 32 rows x 64 halves per panel = 256 16B-chunks; 128 threads x 2
    const int prow = tid >> 2, pcol = (tid & 3) * 16;   // halves
    const uint32_t pdst = (uint32_t)(prow * 72 + pcol) * 2u;
    const uint32_t bufStrideA = 32u * 72u * 2u;
    const uint32_t bufStrideB = 32u * 72u * 2u;

    // issue buffer 0 (k=0) and buffer 1 (k=64)
    {
        const __half* sa = g_wf16 + (d0 + prow) * Fc + 0 + pcol;
        const __half* sb = g_G16  + (n0 + prow) * Fc + 0 + pcol;
        cp16(smA + pdst, sa);      cp16(smA + pdst + 16, sa + 8);
        cp16(smB + pdst, sb);      cp16(smB + pdst + 16, sb + 8);
        cp_commit();
    }
    {
        const __half* sa = g_wf16 + (d0 + prow) * Fc + 64 + pcol;
        const __half* sb = g_G16  + (n0 + prow) * Fc + 64 + pcol;
        cp16(smA + bufStrideA + pdst, sa); cp16(smA + bufStrideA + pdst + 16, sa + 8);
        cp16(smB + bufStrideB + pdst, sb); cp16(smB + bufStrideB + pdst + 16, sb + 8);
        cp_commit();
    }

#pragma unroll
    for (int kb = 0; kb < 8; kb++) {
        cp_wait<1>();
        __syncthreads();

        const uint32_t aB = smA + (uint32_t)(kb & 1) * bufStrideA;
        const uint32_t bB = smB + (uint32_t)(kb & 1) * bufStrideB;
#pragma unroll
        for (int ks = 0; ks < 4; ks++) {
            const uint32_t koff = (uint32_t)(ks * 16) * 2u;
            uint32_t a[4], b[2][2];
            {
                uint32_t addr = aB + aLane + (uint32_t)((wm * 16) * 72) * 2u + koff;
                ldsm_x4(a[0], a[1], a[2], a[3], addr);
            }
            {
                uint32_t t0, t1, t2, t3;
                uint32_t addr = bB + bLane + (uint32_t)((wn * 16) * 72) * 2u + koff;
                ldsm_x4(t0, t1, t2, t3, addr);
                b[0][0] = t0; b[0][1] = t1; b[1][0] = t2; b[1][1] = t3;
            }
            mma16816(acc[0], a, b[0]);
            mma16816(acc[1], a, b[1]);
        }
        __syncthreads();

        // refill the buffer just consumed with k-block kb+2
        if (kb < 6) {
            const int kn = (kb + 2) * 64;
            const uint32_t boff = (uint32_t)(kb & 1);
            const __half* sa = g_wf16 + (d0 + prow) * Fc + kn + pcol;
            const __half* sb = g_G16  + (n0 + prow) * Fc + kn + pcol;
            cp16(smA + boff * bufStrideA + pdst, sa);
            cp16(smA + boff * bufStrideA + pdst + 16, sa + 8);
            cp16(smB + boff * bufStrideB + pdst, sb);
            cp16(smB + boff * bufStrideB + pdst + 16, sb + 8);
            cp_commit();
        } else {
            cp_commit();   // keep group count in sync for cp_wait<1>
        }
    }

    // dkf epilogue (verified structure), accs direct
    const float invF = 1.0f / Fc;
    const int mw = d0 + wm * 16, nw = n0 + wn * 16;
#pragma unroll
    for (int h = 0; h < 2; h++) {
        const int gr = mw + gid + h * 8;
#pragma unroll
        for (int nf = 0; nf < 2; nf++) {
            const int gc = nw + nf * 8 + 2 * tig;
            const int idx = gr * Fc + gc;
            const int cl = gc - n0;
            float v0 = acc[nf][h * 2 + 0];
            float v1 = acc[nf][h * 2 + 1];
            float2 wfv = *(const float2*)&wf32[idx];
            float2 xz  = *(const float2*)&g_XZ[idx];
            float2 o;
            o.x = s_diag[cl] * (xz.x - wfv.x * s_zbar[cl])
                + wfv.x * s_r[cl] - v0 * invF;
            o.y = s_diag[cl + 1] * (xz.y - wfv.y * s_zbar[cl + 1])
                + wfv.y * s_r[cl + 1] - v1 * invF;
            *(float2*)&o_dkf[idx] = o;
        }
    }
}

extern "C" void kernel_launch(void* const* d_in, const int* in_sizes, int n_in,
                              void* d_out, int out_size)
{
    const float* z  = (const float*)d_in[0];   // (B,F)
    const float* x  = (const float*)d_in[1];   // (B,D)
    const float* u  = (const float*)d_in[2];   // (B,F)
    const float* td = (const float*)d_in[3];   // (B,F)
    const float* mu = (const float*)d_in[4];   // (F,F)
    const float* wf = (const float*)d_in[5];   // (D,F)

    float* out   = (float*)d_out;
    float* o_dmu = out;                        // F*F
    float* o_dkf = o_dmu + Fc * Fc;            // D*F
    float* o_dbf = o_dkf + Dc * Fc;            // F
    float* o_dkp = o_dbf + Fc;                 // F*F
    float* o_dbp = o_dkp + Fc * Fc;            // F

    mma1_k<<<176, 256>>>(z, x, u, td, mu, wf, o_dmu, o_dbf, o_dbp, o_dkp);
    mma2_k<<<128, 128>>>(wf, o_dkf);
}

// round 13
// speedup vs baseline: 2.0703x; 1.2186x over previous
#include <cuda_runtime.h>
#include <cuda_fp16.h>
#include <cstdint>

// Problem constants: B=256, D=256, F=512
#define Bc 256
#define Dc 256
#define Fc 512
#define P_T 0.05f

#define DEVARR __device__ __align__(16)
DEVARR __half g_z16[Bc * Fc];
DEVARR __half g_x16[Bc * Dc];
DEVARR __half g_u16[Bc * Fc];
DEVARR __half g_td16[Bc * Fc];
DEVARR __half g_wf16[Dc * Fc];
DEVARR __half g_G16[Fc * Fc];    // G fp16, rows i, cols j
DEVARR float g_XZ[Dc * Fc];      // mean_b x z
DEVARR float g_zbar[Fc];
DEVARR float g_rpart[8][Fc];     // G row-sum partials per 64-col chunk (raw)
DEVARR float g_diag[Fc];         // p - mu_t[i,i]

__device__ __forceinline__ uint32_t smem_u32(const void* p) {
    uint32_t a;
    asm("{ .reg .u64 t; cvta.to.shared.u64 t, %1; cvt.u32.u64 %0, t; }"
        : "=r"(a) : "l"(p));
    return a;
}
// m16n8k16 f16 MMA, fp32 accumulate (verified R7-R12)
__device__ __forceinline__ void mma16816(float* c, const uint32_t* a, const uint32_t* b) {
    asm volatile(
        "mma.sync.aligned.m16n8k16.row.col.f32.f16.f16.f32 "
        "{%0,%1,%2,%3}, {%4,%5,%6,%7}, {%8,%9}, {%0,%1,%2,%3};"
        : "+f"(c[0]), "+f"(c[1]), "+f"(c[2]), "+f"(c[3])
        : "r"(a[0]), "r"(a[1]), "r"(a[2]), "r"(a[3]), "r"(b[0]), "r"(b[1]));
}
__device__ __forceinline__ void ldsm_x4(uint32_t& r0, uint32_t& r1, uint32_t& r2,
                                        uint32_t& r3, uint32_t addr) {
    asm volatile("ldmatrix.sync.aligned.m8n8.x4.shared.b16 {%0,%1,%2,%3}, [%4];"
                 : "=r"(r0), "=r"(r1), "=r"(r2), "=r"(r3) : "r"(addr));
}
__device__ __forceinline__ void ldsm_x4_t(uint32_t& r0, uint32_t& r1, uint32_t& r2,
                                          uint32_t& r3, uint32_t addr) {
    asm volatile("ldmatrix.sync.aligned.m8n8.x4.trans.shared.b16 {%0,%1,%2,%3}, [%4];"
                 : "=r"(r0), "=r"(r1), "=r"(r2), "=r"(r3) : "r"(addr));
}
__device__ __forceinline__ void cp16(uint32_t dst, const void* src) {
    asm volatile("cp.async.cg.shared.global [%0], [%1], 16;" :: "r"(dst), "l"(src));
}
__device__ __forceinline__ void cp_commit() {
    asm volatile("cp.async.commit_group;" ::: "memory");
}
template <int N>
__device__ __forceinline__ void cp_wait() {
    asm volatile("cp.async.wait_group %0;" :: "n"(N) : "memory");
}

// ---------------------------------------------------------------------------
// conv_k: 160 CTAs x 256 threads. [0,144): fp32->fp16 elementwise convert of
// z,x,u,td,wf (no transpose needed - [b][f] is already the [k][m] layout the
// trans-ldmatrix path consumes). [144,160): zbar (fp32-exact).
// ---------------------------------------------------------------------------
__global__ void __launch_bounds__(256) conv_k(
    const float* __restrict__ z, const float* __restrict__ x,
    const float* __restrict__ u, const float* __restrict__ td,
    const float* __restrict__ wf32)
{
    const int bb = blockIdx.x, tid = threadIdx.x;
    if (bb < 144) {
        const float* src; __half* dst; int off0;
        if (bb < 32)       { src = z;    dst = g_z16;  off0 = bb * 4096; }
        else if (bb < 48)  { src = x;    dst = g_x16;  off0 = (bb - 32) * 4096; }
        else if (bb < 80)  { src = u;    dst = g_u16;  off0 = (bb - 48) * 4096; }
        else if (bb < 112) { src = td;   dst = g_td16; off0 = (bb - 80) * 4096; }
        else               { src = wf32; dst = g_wf16; off0 = (bb - 112) * 4096; }
#pragma unroll
        for (int q = 0; q < 4; q++) {
            const int off = off0 + tid * 4 + q * 1024;
            float4 v = *(const float4*)&src[off];
            __half2 h0 = __floats2half2_rn(v.x, v.y);
            __half2 h1 = __floats2half2_rn(v.z, v.w);
            uint2 pk = {*(uint32_t*)&h0, *(uint32_t*)&h1};
            *(uint2*)&dst[off] = pk;
        }
    } else {
        __shared__ float s_z[8][33];
        const int zc = tid & 31, zr = tid >> 5;   // zr 0..7
        const int col = (bb - 144) * 32 + zc;
        float s = 0.f;
#pragma unroll
        for (int i = 0; i < 32; i++) s += z[(zr + 8 * i) * Fc + col];
        s_z[zr][zc] = s;
        __syncthreads();
        if (tid < 32) {
            float t = 0.f;
#pragma unroll
            for (int p = 0; p < 8; p++) t += s_z[p][tid];
            g_zbar[(bb - 144) * 32 + tid] = t * (1.0f / Bc);
        }
    }
}

// ---------------------------------------------------------------------------
// mma1_k: 160 CTAs x 256 threads. 64x64 tiles, K=256 as 8 k-blocks of 32,
// 4-stage cp.async pipeline on fp16 panels. 8 warps (2x4), warp 32x16.
//  bb [0,64):    M  = z'z /B  -> dmu, G16, rpart, diag/dbf/dbp
//  bb [64,128):  KP = u'td /B -> o_dkp
//  bb [128,160): XZ = x'z /B  -> g_XZ
// ---------------------------------------------------------------------------
__global__ void __launch_bounds__(256) mma1_k(
    const float* __restrict__ mu,
    float* __restrict__ o_dmu, float* __restrict__ o_dbf,
    float* __restrict__ o_dbp, float* __restrict__ o_dkp)
{
    __shared__ __align__(16) __half As[4][32][72];   // [stage][k][m]
    __shared__ __align__(16) __half Bs[4][32][72];   // [stage][k][n]
    __shared__ float s_rsum[64];

    const int bb = blockIdx.x, tid = threadIdx.x;
    const int wig = tid >> 5, lane = tid & 31;
    const int gid = lane >> 2, tig = lane & 3;
    const int wm = wig >> 2, wn = wig & 3;        // 2x4 warp grid
    const int q = lane >> 3, r = lane & 7;

    int kind, m0, n0, lda;
    const __half *A, *B;
    if (bb < 64)       { kind = 0; int t = bb;       m0 = (t >> 3) * 64; n0 = (t & 7) * 64; A = g_z16; B = g_z16;  lda = Fc; }
    else if (bb < 128) { kind = 1; int t = bb - 64;  m0 = (t >> 3) * 64; n0 = (t & 7) * 64; A = g_u16; B = g_td16; lda = Fc; }
    else               { kind = 2; int t = bb - 128; m0 = (t >> 3) * 64; n0 = (t & 7) * 64; A = g_x16; B = g_z16;  lda = Dc; }

    if (tid < 64) s_rsum[tid] = 0.f;

    float acc[2][2][4];
#pragma unroll
    for (int i = 0; i < 2; i++)
#pragma unroll
        for (int j = 0; j < 2; j++)
#pragma unroll
            for (int p = 0; p < 4; p++) acc[i][j][p] = 0.f;

    const uint32_t smA = smem_u32(As), smB = smem_u32(Bs);
    const uint32_t aLane = (uint32_t)(((((q & 2) ? 8 : 0) + r) * 72 + ((q & 1) ? 8 : 0)) * 2);
    const uint32_t bLane = (uint32_t)(((((q & 1) ? 8 : 0) + r) * 72 + ((q & 2) ? 8 : 0)) * 2);
    const uint32_t STB = 32u * 72u * 2u;          // stage stride bytes

    // cp.async mapping: 32 k-rows x 64 halves; 256 threads x 16B each.
    const int prow = tid >> 3, pcol = (tid & 7) * 8;   // halves
    const uint32_t pdst = (uint32_t)(prow * 72 + pcol) * 2u;

    // prologue: issue blocks 0,1,2
#pragma unroll
    for (int s = 0; s < 3; s++) {
        cp16(smA + (uint32_t)s * STB + pdst, A + (s * 32 + prow) * lda + m0 + pcol);
        cp16(smB + (uint32_t)s * STB + pdst, B + (s * 32 + prow) * Fc  + n0 + pcol);
        cp_commit();
    }

#pragma unroll
    for (int kb = 0; kb < 8; kb++) {
        cp_wait<2>();
        __syncthreads();
        if (kb + 3 < 8) {
            const int kr = (kb + 3) * 32 + prow;
            const uint32_t so = (uint32_t)((kb + 3) & 3) * STB;
            cp16(smA + so + pdst, A + kr * lda + m0 + pcol);
            cp16(smB + so + pdst, B + kr * Fc  + n0 + pcol);
        }
        cp_commit();

        const uint32_t aB = smA + (uint32_t)(kb & 3) * STB;
        const uint32_t bB = smB + (uint32_t)(kb & 3) * STB;
#pragma unroll
        for (int ks = 0; ks < 2; ks++) {
            const uint32_t koff = (uint32_t)(ks * 16) * 72u * 2u;
            uint32_t a[2][4], b[2][2];
#pragma unroll
            for (int mf = 0; mf < 2; mf++) {
                uint32_t addr = aB + aLane + koff + (uint32_t)(wm * 32 + mf * 16) * 2u;
                ldsm_x4_t(a[mf][0], a[mf][1], a[mf][2], a[mf][3], addr);
            }
            {
                uint32_t t0, t1, t2, t3;
                uint32_t addr = bB + bLane + koff + (uint32_t)(wn * 16) * 2u;
                ldsm_x4_t(t0, t1, t2, t3, addr);
                b[0][0] = t0; b[0][1] = t1;
                b[1][0] = t2; b[1][1] = t3;
            }
#pragma unroll
            for (int mf = 0; mf < 2; mf++)
#pragma unroll
                for (int nf = 0; nf < 2; nf++)
                    mma16816(acc[mf][nf], a[mf], b[nf]);
        }
    }
    __syncthreads();

    // Fused epilogue (verified R12)
    const int mw = m0 + wm * 32, nw = n0 + wn * 16;
    const float invB = 1.0f / Bc;
#pragma unroll
    for (int mf = 0; mf < 2; mf++) {
#pragma unroll
        for (int h = 0; h < 2; h++) {
            const int gr = mw + mf * 16 + gid + h * 8;
            float rowsum = 0.f;
#pragma unroll
            for (int nf = 0; nf < 2; nf++) {
                const int gc = nw + nf * 8 + 2 * tig;
                const int idx = gr * Fc + gc;
                float v0 = acc[mf][nf][h * 2 + 0];
                float v1 = acc[mf][nf][h * 2 + 1];
                if (kind == 0) {
                    float raw0 = v0 * invB, raw1 = v1 * invB;
                    float2 muv = *(const float2*)&mu[idx];
                    float mut0 = 0.95f * muv.x + 0.05f * raw0;
                    float mut1 = 0.95f * muv.y + 0.05f * raw1;
                    float2 dm = {0.05f * (raw0 - muv.x), 0.05f * (raw1 - muv.y)};
                    *(float2*)&o_dmu[idx] = dm;
                    float G0 = (P_T * P_T - mut0) * raw0;
                    float G1 = (P_T * P_T - mut1) * raw1;
                    *(__half2*)&g_G16[idx] = __floats2half2_rn(G0, G1);
                    rowsum += G0 + G1;
                    if (m0 == n0) {
                        if (gr == gc) {
                            float db = P_T - mut0;
                            g_diag[gr] = db; o_dbf[gr] = db; o_dbp[gr] = db;
                        } else if (gr == gc + 1) {
                            float db = P_T - mut1;
                            g_diag[gr] = db; o_dbf[gr] = db; o_dbp[gr] = db;
                        }
                    }
                } else if (kind == 1) {
                    float2 o = {v0 * invB, v1 * invB};
                    *(float2*)&o_dkp[idx] = o;
                } else {
                    float2 o = {v0 * invB, v1 * invB};
                    *(float2*)&g_XZ[idx] = o;
                }
            }
            if (kind == 0) {
                rowsum += __shfl_xor_sync(0xffffffffu, rowsum, 1);
                rowsum += __shfl_xor_sync(0xffffffffu, rowsum, 2);
                if (tig == 0) atomicAdd(&s_rsum[gr - m0], rowsum);
            }
        }
    }
    if (kind == 0) {
        __syncthreads();
        if (tid < 64) g_rpart[n0 >> 6][m0 + tid] = s_rsum[tid];
    }
}

// ---------------------------------------------------------------------------
// mma2_k: 128 CTAs x 128 threads. 32x32 tiles, K=512 as 8 k-blocks of 64,
// 4-stage cp.async pipeline. 4 warps (2x2), warp 16x16 (nf=2). dkf fused.
// ---------------------------------------------------------------------------
__global__ void __launch_bounds__(128) mma2_k(
    const float* __restrict__ wf32, float* __restrict__ o_dkf)
{
    __shared__ __align__(16) __half As[4][32][72];   // [stage][m=32][k=64]
    __shared__ __align__(16) __half Bs[4][32][72];   // [stage][n=32][k=64]
    __shared__ float s_diag[32], s_zbar[32], s_r[32];

    const int bb = blockIdx.x, tid = threadIdx.x;
    const int wig = tid >> 5, lane = tid & 31;
    const int gid = lane >> 2, tig = lane & 3;
    const int wm = wig >> 1, wn = wig & 1;        // 2x2 warp grid
    const int q = lane >> 3, r = lane & 7;

    const int d0 = (bb >> 4) * 32;                // 8 d-tiles
    const int n0 = (bb & 15) * 32;                // 16 n-tiles

    if (tid < 32) {
        int i = n0 + tid;
        s_zbar[tid] = g_zbar[i];
        float rr = 0.f;
#pragma unroll
        for (int p = 0; p < 8; p++) rr += g_rpart[p][i];
        s_r[tid] = rr * (1.0f / Fc);
        s_diag[tid] = g_diag[i];
    }

    float acc[2][4];
#pragma unroll
    for (int j = 0; j < 2; j++)
#pragma unroll
        for (int p = 0; p < 4; p++) acc[j][p] = 0.f;

    const uint32_t smA = smem_u32(As), smB = smem_u32(Bs);
    const uint32_t aLane = (uint32_t)(((((q & 1) ? 8 : 0) + r) * 72 + ((q & 2) ? 8 : 0)) * 2);
    const uint32_t bLane = (uint32_t)(((((q & 2) ? 8 : 0) + r) * 72 + ((q & 1) ? 8 : 0)) * 2);
    const uint32_t STB = 32u * 72u * 2u;

    // cp.async: 32 rows x 64 halves = 256 16B chunks; 128 threads x 2 chunks
    const int prow = tid >> 2, pcol = (tid & 3) * 16;
    const uint32_t pdst = (uint32_t)(prow * 72 + pcol) * 2u;

    // prologue: blocks 0,1,2
#pragma unroll
    for (int s = 0; s < 3; s++) {
        const __half* sa = g_wf16 + (d0 + prow) * Fc + s * 64 + pcol;
        const __half* sb = g_G16  + (n0 + prow) * Fc + s * 64 + pcol;
        const uint32_t so = (uint32_t)s * STB;
        cp16(smA + so + pdst, sa); cp16(smA + so + pdst + 16, sa + 8);
        cp16(smB + so + pdst, sb); cp16(smB + so + pdst + 16, sb + 8);
        cp_commit();
    }

#pragma unroll
    for (int kb = 0; kb < 8; kb++) {
        cp_wait<2>();
        __syncthreads();
        if (kb + 3 < 8) {
            const int kn = (kb + 3) * 64;
            const uint32_t so = (uint32_t)((kb + 3) & 3) * STB;
            const __half* sa = g_wf16 + (d0 + prow) * Fc + kn + pcol;
            const __half* sb = g_G16  + (n0 + prow) * Fc + kn + pcol;
            cp16(smA + so + pdst, sa); cp16(smA + so + pdst + 16, sa + 8);
            cp16(smB + so + pdst, sb); cp16(smB + so + pdst + 16, sb + 8);
        }
        cp_commit();

        const uint32_t aB = smA + (uint32_t)(kb & 3) * STB;
        const uint32_t bB = smB + (uint32_t)(kb & 3) * STB;
#pragma unroll
        for (int ks = 0; ks < 4; ks++) {
            const uint32_t koff = (uint32_t)(ks * 16) * 2u;
            uint32_t a[4], b[2][2];
            {
                uint32_t addr = aB + aLane + (uint32_t)((wm * 16) * 72) * 2u + koff;
                ldsm_x4(a[0], a[1], a[2], a[3], addr);
            }
            {
                uint32_t t0, t1, t2, t3;
                uint32_t addr = bB + bLane + (uint32_t)((wn * 16) * 72) * 2u + koff;
                ldsm_x4(t0, t1, t2, t3, addr);
                b[0][0] = t0; b[0][1] = t1; b[1][0] = t2; b[1][1] = t3;
            }
            mma16816(acc[0], a, b[0]);
            mma16816(acc[1], a, b[1]);
        }
    }

    // dkf epilogue (verified R12)
    const float invF = 1.0f / Fc;
    const int mw = d0 + wm * 16, nw = n0 + wn * 16;
#pragma unroll
    for (int h = 0; h < 2; h++) {
        const int gr = mw + gid + h * 8;
#pragma unroll
        for (int nf = 0; nf < 2; nf++) {
            const int gc = nw + nf * 8 + 2 * tig;
            const int idx = gr * Fc + gc;
            const int cl = gc - n0;
            float v0 = acc[nf][h * 2 + 0];
            float v1 = acc[nf][h * 2 + 1];
            float2 wfv = *(const float2*)&wf32[idx];
            float2 xz  = *(const float2*)&g_XZ[idx];
            float2 o;
            o.x = s_diag[cl] * (xz.x - wfv.x * s_zbar[cl])
                + wfv.x * s_r[cl] - v0 * invF;
            o.y = s_diag[cl + 1] * (xz.y - wfv.y * s_zbar[cl + 1])
                + wfv.y * s_r[cl + 1] - v1 * invF;
            *(float2*)&o_dkf[idx] = o;
        }
    }
}

extern "C" void kernel_launch(void* const* d_in, const int* in_sizes, int n_in,
                              void* d_out, int out_size)
{
    const float* z  = (const float*)d_in[0];   // (B,F)
    const float* x  = (const float*)d_in[1];   // (B,D)
    const float* u  = (const float*)d_in[2];   // (B,F)
    const float* td = (const float*)d_in[3];   // (B,F)
    const float* mu = (const float*)d_in[4];   // (F,F)
    const float* wf = (const float*)d_in[5];   // (D,F)

    float* out   = (float*)d_out;
    float* o_dmu = out;                        // F*F
    float* o_dkf = o_dmu + Fc * Fc;            // D*F
    float* o_dbf = o_dkf + Dc * Fc;            // F
    float* o_dkp = o_dbf + Fc;                 // F*F
    float* o_dbp = o_dkp + Fc * Fc;            // F

    conv_k<<<160, 256>>>(z, x, u, td, wf);
    mma1_k<<<160, 256>>>(mu, o_dmu, o_dbf, o_dbp, o_dkp);
    mma2_k<<<128, 128>>>(wf, o_dkf);
}